// round 7
// baseline (speedup 1.0000x reference)
#include <cuda_runtime.h>
#include <math_constants.h>

// attention_FCN: B=512, S=512, F=128, H1=80, H2=40
// din@W2 = qpre(b) + f @ Weff(b),  Weff = (W2b - W2c) + diag(q_b) @ W2d
// Round 6: weights read via warp-UNIFORM LDG (L2 scratch) -> near-zero smem
// wavefronts for B operand; all LDS are 32-distinct-lane conflict-free;
// 256 thr x 3 CTAs/SM; f32x2 packed FMA; online softmax; facts read once.

#define Bn   512
#define Sn   512
#define Fn   128
#define H1n  80
#define H2n  40
#define TSn  64
#define NTn  (Sn / TSn)
#define FSTRIDE 132    // 132/4=33 odd -> LDS.128 lane-rows conflict-free
#define H1S     84     // 84/4=21 odd  -> conflict-free
#define PADV (-4294967295.0f)

__device__ float g_weff[Bn * H1n * Fn];   // per-batch Weff, [b][h1][k], 21 MB (L2)
__device__ float g_w3T[H2n * H1n];        // W3 transposed: [h2][k]

__device__ __forceinline__ unsigned long long pk2(float lo, float hi) {
    unsigned long long r;
    asm("mov.b64 %0, {%1,%2};" : "=l"(r) : "f"(lo), "f"(hi));
    return r;
}
__device__ __forceinline__ float2 upk2(unsigned long long v) {
    float2 r;
    asm("mov.b64 {%0,%1}, %2;" : "=f"(r.x), "=f"(r.y) : "l"(v));
    return r;
}
#define FMA2(d, a, b) \
    asm("fma.rn.f32x2 %0, %1, %2, %0;" : "+l"(d) : "l"(a), "l"(b))

__device__ __forceinline__ float fsigmoid(float x) {
    return __fdividef(1.f, 1.f + __expf(-x));
}

// ---------------------------------------------------------------------------
__global__ __launch_bounds__(256) void setup_w3_kernel(const float* __restrict__ W3)
{
    const int i = blockIdx.x * 256 + threadIdx.x;
    if (i < H1n * H2n) {
        const int h2 = i / H1n, k = i - h2 * H1n;
        g_w3T[i] = W3[k * H2n + h2];
    }
}

// ---------------------------------------------------------------------------
__global__ __launch_bounds__(256, 3) void din_kernel(
    const float* __restrict__ query,
    const float* __restrict__ facts,
    const int*   __restrict__ mask,
    const float* __restrict__ W1,
    const float* __restrict__ b1,
    const float* __restrict__ alpha,
    const float* __restrict__ W2,
    const float* __restrict__ b2,
    const float* __restrict__ b3,
    const float* __restrict__ W4,
    const float* __restrict__ b4,
    float* __restrict__ out)
{
    extern __shared__ float dyn[];
    float* fsm  = dyn;                  // TSn*FSTRIDE = 8448 f  (33.8 KB)
    float* h1sm = fsm + TSn * FSTRIDE;  // TSn*H1S     = 5376 f  (21.5 KB)

    __shared__ float qsm[Fn];
    __shared__ float qprem[H1n];
    __shared__ float w4sm[H2n];
    __shared__ float b3sm[H2n];
    __shared__ float psm[8 * TSn];      // per-warp score partials
    __shared__ float sbuf[TSn];         // masked scores
    __shared__ float wsm[TSn];          // softmax weights
    __shared__ float red[2];
    __shared__ float s_m, s_l, s_scale, s_b4;

    const int b    = blockIdx.x;
    const int tid  = threadIdx.x;
    const int lane = tid & 31;
    const int warp = tid >> 5;

    // ---- prologue: q = PReLU(query@W1+b1) ----
    if (tid < Fn) qsm[tid] = query[b * Fn + tid];   // reuse qsm as qin first
    if (tid == 0) { s_m = -CUDART_INF_F; s_l = 0.f; s_b4 = b4[0]; }
    if (tid < H2n) { w4sm[tid] = W4[tid]; b3sm[tid] = b3[tid]; }
    __syncthreads();
    float qv = 0.f;
    if (tid < Fn) {
        float a0 = b1[tid], a1 = 0.f, a2 = 0.f, a3 = 0.f;
#pragma unroll 4
        for (int k = 0; k < Fn; k += 4) {
            a0 = fmaf(qsm[k + 0], W1[(k + 0) * Fn + tid], a0);
            a1 = fmaf(qsm[k + 1], W1[(k + 1) * Fn + tid], a1);
            a2 = fmaf(qsm[k + 2], W1[(k + 2) * Fn + tid], a2);
            a3 = fmaf(qsm[k + 3], W1[(k + 3) * Fn + tid], a3);
        }
        const float acc = (a0 + a1) + (a2 + a3);
        qv = (acc >= 0.f) ? acc : alpha[tid] * acc;
    }
    __syncthreads();
    if (tid < Fn) qsm[tid] = qv;
    __syncthreads();

    // qpre[h] = b2[h] + sum_k q[k]*(W2a+W2c)[k,h]
    if (tid < H1n) {
        float a0 = b2[tid], a1 = 0.f;
#pragma unroll 4
        for (int k = 0; k < Fn; k += 2) {
            a0 = fmaf(qsm[k+0], W2[(k+0)*H1n + tid] + W2[(2*Fn + k+0)*H1n + tid], a0);
            a1 = fmaf(qsm[k+1], W2[(k+1)*H1n + tid] + W2[(2*Fn + k+1)*H1n + tid], a1);
        }
        qprem[tid] = a0 + a1;
    }
    // g_weff[b][h][k] = (W2b - W2c)[k,h] + q[k]*W2d[k,h]   (k-contiguous rows)
    {
        float* wout = g_weff + b * (H1n * Fn);
        for (int i = tid; i < Fn * H1n; i += 256) {
            const int h = i >> 7, k = i & 127;
            const float wbc = W2[(Fn + k) * H1n + h] - W2[(2 * Fn + k) * H1n + h];
            const float wd  = W2[(3 * Fn + k) * H1n + h];
            wout[i] = fmaf(qsm[k], wd, wbc);
        }
    }
    __syncthreads();   // weff visible block-wide (global, block-scope fence)

    const float* weffb = g_weff + b * (H1n * Fn) + (warp * 10) * Fn;
    const float* w3b   = g_w3T + (warp * 5) * H1n;

    float racc = 0.f;                 // epilogue accumulator (f = tid&127)
    const int ef = tid & 127, eh = tid >> 7;

    for (int t = 0; t < NTn; t++) {
        // ---- facts tile [64,128] -> smem ----
        const float4* fp = (const float4*)(facts + (size_t)(b * Sn + t * TSn) * Fn);
        for (int i = tid; i < TSn * (Fn / 4); i += 256) {
            const int r = i >> 5, c4 = i & 31;
            *(float4*)(fsm + r * FSTRIDE + c4 * 4) = fp[r * 32 + c4];
        }
        __syncthreads();

        // ---- GEMM1: rows {lane, lane+32}, cols warp*10..+9 (uniform LDG) ----
        {
            unsigned long long acc[2][10];
#pragma unroll
            for (int j = 0; j < 10; j++) {
                const unsigned long long z = pk2(qprem[warp * 10 + j], 0.f);
                acc[0][j] = z; acc[1][j] = z;
            }
            const float* f0 = fsm + lane * FSTRIDE;
            const float* f1 = fsm + (lane + 32) * FSTRIDE;
#pragma unroll 2
            for (int k = 0; k < Fn; k += 4) {
                const ulonglong2 a0 = *(const ulonglong2*)(f0 + k);
                const ulonglong2 a1 = *(const ulonglong2*)(f1 + k);
#pragma unroll
                for (int j = 0; j < 10; j++) {
                    const ulonglong2 bv = *(const ulonglong2*)(weffb + j * Fn + k);
                    FMA2(acc[0][j], a0.x, bv.x);
                    FMA2(acc[0][j], a0.y, bv.y);
                    FMA2(acc[1][j], a1.x, bv.x);
                    FMA2(acc[1][j], a1.y, bv.y);
                }
            }
            float* h0 = h1sm + lane * H1S + warp * 10;
            float* h1 = h1sm + (lane + 32) * H1S + warp * 10;
#pragma unroll
            for (int j = 0; j < 5; j++) {
                float2 o0, o1;
                const float2 u0 = upk2(acc[0][2*j]),   v0 = upk2(acc[0][2*j+1]);
                const float2 u1 = upk2(acc[1][2*j]),   v1 = upk2(acc[1][2*j+1]);
                o0.x = fsigmoid(u0.x + u0.y); o0.y = fsigmoid(v0.x + v0.y);
                o1.x = fsigmoid(u1.x + u1.y); o1.y = fsigmoid(v1.x + v1.y);
                *(float2*)(h0 + 2*j) = o0;
                *(float2*)(h1 + 2*j) = o1;
            }
        }
        __syncthreads();

        // ---- GEMM2 + score partials: rows {lane, lane+32}, cols warp*5..+4 ----
        {
            unsigned long long acc[2][5];
#pragma unroll
            for (int j = 0; j < 5; j++) {
                const unsigned long long z = pk2(b3sm[warp * 5 + j], 0.f);
                acc[0][j] = z; acc[1][j] = z;
            }
            const float* h0 = h1sm + lane * H1S;
            const float* h1 = h1sm + (lane + 32) * H1S;
#pragma unroll 2
            for (int k = 0; k < H1n; k += 4) {
                const ulonglong2 a0 = *(const ulonglong2*)(h0 + k);
                const ulonglong2 a1 = *(const ulonglong2*)(h1 + k);
#pragma unroll
                for (int j = 0; j < 5; j++) {
                    const ulonglong2 wv = *(const ulonglong2*)(w3b + j * H1n + k);
                    FMA2(acc[0][j], a0.x, wv.x);
                    FMA2(acc[0][j], a0.y, wv.y);
                    FMA2(acc[1][j], a1.x, wv.x);
                    FMA2(acc[1][j], a1.y, wv.y);
                }
            }
            float p0 = 0.f, p1 = 0.f;
#pragma unroll
            for (int j = 0; j < 5; j++) {
                const float wj = w4sm[warp * 5 + j];
                const float2 u0 = upk2(acc[0][j]), u1 = upk2(acc[1][j]);
                p0 = fmaf(fsigmoid(u0.x + u0.y), wj, p0);
                p1 = fmaf(fsigmoid(u1.x + u1.y), wj, p1);
            }
            psm[warp * TSn + lane]      = p0;
            psm[warp * TSn + lane + 32] = p1;
        }
        __syncthreads();

        // ---- warp 0: scores + mask + tile max + running max/scale ----
        if (tid < 32) {
            float sa = s_b4, sb = s_b4;
#pragma unroll
            for (int w = 0; w < 8; w++) {
                sa += psm[w * TSn + tid];
                sb += psm[w * TSn + tid + 32];
            }
            const int mbase = b * Sn + t * TSn;
            sa = (mask[mbase + tid]      == 1) ? sa : PADV;
            sb = (mask[mbase + tid + 32] == 1) ? sb : PADV;
            sbuf[tid]      = sa;
            sbuf[tid + 32] = sb;
            float m4 = fmaxf(sa, sb);
#pragma unroll
            for (int off = 16; off; off >>= 1)
                m4 = fmaxf(m4, __shfl_xor_sync(0xffffffffu, m4, off));
            if (tid == 0) {
                const float nm = fmaxf(s_m, m4);
                s_scale = __expf(s_m - nm);   // 0 on first tile
                s_m = nm;
            }
        }
        __syncthreads();

        // ---- weights + tile sum ----
        float wv = 0.f;
        if (tid < TSn) {
            wv = __expf(sbuf[tid] - s_m);
            wsm[tid] = wv;
        }
#pragma unroll
        for (int off = 16; off; off >>= 1)
            wv += __shfl_xor_sync(0xffffffffu, wv, off);
        if (tid < TSn && lane == 0) red[tid >> 5] = wv;
        __syncthreads();

        if (tid == 0) s_l = s_l * s_scale + red[0] + red[1];
        // ---- epilogue: racc over this tile (all 256 threads) ----
        {
            float a = racc * s_scale;
            const float* fc = fsm + ef + (eh * 32) * FSTRIDE;
            const float* wc = wsm + eh * 32;
#pragma unroll 8
            for (int s = 0; s < 32; s++)
                a = fmaf(wc[s], fc[s * FSTRIDE], a);
            racc = a;
        }
        __syncthreads();   // protect fsm/wsm before next tile load
    }

    // combine the two s-halves and write out
    if (eh == 1) psm[ef] = racc;
    __syncthreads();
    if (eh == 0)
        out[b * Fn + ef] = (racc + psm[ef]) / s_l;
}

// ---------------------------------------------------------------------------
extern "C" void kernel_launch(void* const* d_in, const int* in_sizes, int n_in,
                              void* d_out, int out_size)
{
    const float* query = (const float*)d_in[0];
    const float* facts = (const float*)d_in[1];
    const int*   mask  = (const int*)  d_in[2];
    const float* W1    = (const float*)d_in[3];
    const float* b1    = (const float*)d_in[4];
    const float* alpha = (const float*)d_in[5];
    const float* W2    = (const float*)d_in[6];
    const float* b2    = (const float*)d_in[7];
    const float* W3    = (const float*)d_in[8];
    const float* b3    = (const float*)d_in[9];
    const float* W4    = (const float*)d_in[10];
    const float* b4    = (const float*)d_in[11];
    float* out = (float*)d_out;

    const int dyn_smem = (TSn * FSTRIDE + TSn * H1S) * (int)sizeof(float); // 55296 B
    cudaFuncSetAttribute(din_kernel,
                         cudaFuncAttributeMaxDynamicSharedMemorySize, dyn_smem);

    setup_w3_kernel<<<(H1n * H2n + 255) / 256, 256>>>(W3);
    din_kernel<<<Bn, 256, dyn_smem>>>(query, facts, mask, W1, b1, alpha,
                                      W2, b2, b3, W4, b4, out);
}

// round 9
// speedup vs baseline: 1.1750x; 1.1750x over previous
#include <cuda_runtime.h>
#include <math_constants.h>

// attention_FCN: B=512, S=512, F=128, H1=80, H2=40
// din@W2 = qpre(b) + f @ Weff(b),  Weff = (W2b - W2c) + diag(q_b) @ W2d
// Round 8: 128 thr/CTA, 2 CTA/SM, big per-thread tiles (GEMM1 8x5, GEMM2 4x5),
// all operands in smem, f32x2 k-packed FMA, S split across 2 CTAs per batch
// (flash partials + combine kernel).

#define Bn   512
#define Sn   512
#define Fn   128
#define H1n  80
#define H2n  40
#define TSn  64
#define NTn  4          // tiles per CTA (S-half = 256 = 4*64)
#define FSTRIDE 132     // facts: 132%32=4 -> 8 distinct lane-rows conflict-free
#define WS      128     // weffT row stride (broadcast reads; alignment only)
#define H1S     84      // h1: 84%32=20 -> conflict-free lane rows
#define W3S     80      // w3T row stride (broadcast reads)
#define PARTW   132     // partial record: 128 acc + m + l (+pad)
#define PADV (-4294967295.0f)

__device__ float g_part[Bn * 2 * PARTW];

__device__ __forceinline__ unsigned long long pk2(float lo, float hi) {
    unsigned long long r;
    asm("mov.b64 %0, {%1,%2};" : "=l"(r) : "f"(lo), "f"(hi));
    return r;
}
__device__ __forceinline__ float2 upk2(unsigned long long v) {
    float2 r;
    asm("mov.b64 {%0,%1}, %2;" : "=f"(r.x), "=f"(r.y) : "l"(v));
    return r;
}
#define FMA2(d, a, b) \
    asm("fma.rn.f32x2 %0, %1, %2, %0;" : "+l"(d) : "l"(a), "l"(b))

__device__ __forceinline__ float fsigmoid(float x) {
    return __fdividef(1.f, 1.f + __expf(-x));
}

// ---------------------------------------------------------------------------
__global__ __launch_bounds__(128, 2) void din_kernel(
    const float* __restrict__ query,
    const float* __restrict__ facts,
    const int*   __restrict__ mask,
    const float* __restrict__ W1,
    const float* __restrict__ b1,
    const float* __restrict__ alpha,
    const float* __restrict__ W2,
    const float* __restrict__ b2,
    const float* __restrict__ W3,
    const float* __restrict__ b3,
    const float* __restrict__ W4,
    const float* __restrict__ b4)
{
    extern __shared__ float dyn[];
    float* fsm   = dyn;                       // 64*132 = 8448 f
    float* weffT = fsm + TSn * FSTRIDE;       // 80*128 = 10240 f (k-major)
    float* h1sm  = weffT + H1n * WS;          // 64*84  = 5376 f
    float* w3T   = h1sm + TSn * H1S;          // 40*80  = 3200 f (k-major)

    __shared__ float qsm[Fn];
    __shared__ float qprem[H1n];
    __shared__ float w4sm[H2n];
    __shared__ float b3sm[H2n];
    __shared__ float psm[128];       // GEMM2 partials: [wc*64 + row]
    __shared__ float sbuf[TSn];      // masked scores
    __shared__ float wsm[TSn];       // softmax weights
    __shared__ float red[2];
    __shared__ float s_m, s_l, s_scale, s_b4;

    const int cta  = blockIdx.x;
    const int b    = cta >> 1;
    const int half = cta & 1;
    const int tid  = threadIdx.x;
    const int lane = tid & 31;
    const int warp = tid >> 5;
    const int lrow = lane & 7;       // 8 lane-rows
    const int lcol = lane >> 3;      // 4 lane-cols

    // ---- prologue ----
    qsm[tid] = query[b * Fn + tid];
    if (tid == 0) { s_m = -CUDART_INF_F; s_l = 0.f; s_b4 = b4[0]; }
    if (tid < H2n) { w4sm[tid] = W4[tid]; b3sm[tid] = b3[tid]; }
    for (int i = tid; i < H1n * H2n; i += 128) {     // w3T[h2][k] = W3[k][h2]
        const int h2 = i % H2n, k = i / H2n;
        w3T[h2 * W3S + k] = W3[i];
    }
    __syncthreads();

    // q = PReLU(query @ W1 + b1)
    float qv;
    {
        float a0 = b1[tid], a1 = 0.f, a2 = 0.f, a3 = 0.f;
#pragma unroll 4
        for (int k = 0; k < Fn; k += 4) {
            a0 = fmaf(qsm[k + 0], W1[(k + 0) * Fn + tid], a0);
            a1 = fmaf(qsm[k + 1], W1[(k + 1) * Fn + tid], a1);
            a2 = fmaf(qsm[k + 2], W1[(k + 2) * Fn + tid], a2);
            a3 = fmaf(qsm[k + 3], W1[(k + 3) * Fn + tid], a3);
        }
        const float acc = (a0 + a1) + (a2 + a3);
        qv = (acc >= 0.f) ? acc : alpha[tid] * acc;
    }
    __syncthreads();
    qsm[tid] = qv;
    __syncthreads();

    // qpre[h] = b2[h] + sum_k q[k]*(W2a+W2c)[k,h]
    if (tid < H1n) {
        float a0 = b2[tid], a1 = 0.f;
#pragma unroll 4
        for (int k = 0; k < Fn; k += 2) {
            a0 = fmaf(qsm[k+0], W2[(k+0)*H1n + tid] + W2[(2*Fn + k+0)*H1n + tid], a0);
            a1 = fmaf(qsm[k+1], W2[(k+1)*H1n + tid] + W2[(2*Fn + k+1)*H1n + tid], a1);
        }
        qprem[tid] = a0 + a1;
    }
    // weffT[h][k] = (W2b - W2c)[k,h] + q[k]*W2d[k,h]  (coalesced over h)
    for (int i = tid; i < Fn * H1n; i += 128) {
        const int h = i % H1n, k = i / H1n;
        const float wbc = W2[(Fn + k) * H1n + h] - W2[(2 * Fn + k) * H1n + h];
        const float wd  = W2[(3 * Fn + k) * H1n + h];
        weffT[h * WS + k] = fmaf(qsm[k], wd, wbc);
    }
    __syncthreads();

    const int sbase = half * (Sn / 2);
    float racc = 0.f;                        // epilogue acc, f = tid

    for (int t = 0; t < NTn; t++) {
        // ---- facts tile [64,128] -> smem ----
        const float4* fp = (const float4*)(facts + (size_t)(b * Sn + sbase + t * TSn) * Fn);
        for (int i = tid; i < TSn * (Fn / 4); i += 128) {
            const int r = i >> 5, c4 = i & 31;
            *(float4*)(fsm + r * FSTRIDE + c4 * 4) = fp[r * 32 + c4];
        }
        __syncthreads();

        // ---- GEMM1: thread tile 8 rows x 5 cols, k-packed f32x2 ----
        // warp w -> cols [w*20, w*20+20); lcol -> +5*lcol; rows = lrow + 8i
        {
            const int col0 = warp * 20 + lcol * 5;
            unsigned long long acc[8][5];
#pragma unroll
            for (int j = 0; j < 5; j++) {
                const unsigned long long z = pk2(qprem[col0 + j], 0.f);
#pragma unroll
                for (int i = 0; i < 8; i++) acc[i][j] = z;
            }
            const float* fr = fsm + lrow * FSTRIDE;
            const float* wb = weffT + col0 * WS;
#pragma unroll 2
            for (int k = 0; k < Fn; k += 4) {
                ulonglong2 av[8], bv[5];
#pragma unroll
                for (int i = 0; i < 8; i++)
                    av[i] = *(const ulonglong2*)(fr + (i * 8) * FSTRIDE + k);
#pragma unroll
                for (int j = 0; j < 5; j++)
                    bv[j] = *(const ulonglong2*)(wb + j * WS + k);
#pragma unroll
                for (int i = 0; i < 8; i++)
#pragma unroll
                    for (int j = 0; j < 5; j++) {
                        FMA2(acc[i][j], av[i].x, bv[j].x);
                        FMA2(acc[i][j], av[i].y, bv[j].y);
                    }
            }
#pragma unroll
            for (int i = 0; i < 8; i++) {
                float* hb = h1sm + (lrow + 8 * i) * H1S + col0;
#pragma unroll
                for (int j = 0; j < 5; j++) {
                    const float2 v = upk2(acc[i][j]);
                    hb[j] = fsigmoid(v.x + v.y);
                }
            }
        }
        __syncthreads();

        // ---- GEMM2 + score: thread tile 4 rows x 5 cols ----
        // warp: wr = row half (32), wc = col half (20); rows = wr*32+lrow+8i
        {
            const int wr = warp & 1, wc = warp >> 1;
            const int col0 = wc * 20 + lcol * 5;
            const int row0 = wr * 32 + lrow;
            unsigned long long acc[4][5];
#pragma unroll
            for (int j = 0; j < 5; j++) {
                const unsigned long long z = pk2(b3sm[col0 + j], 0.f);
#pragma unroll
                for (int i = 0; i < 4; i++) acc[i][j] = z;
            }
            const float* hr = h1sm + row0 * H1S;
            const float* wc3 = w3T + col0 * W3S;
#pragma unroll 2
            for (int k = 0; k < H1n; k += 4) {
                ulonglong2 av[4], bv[5];
#pragma unroll
                for (int i = 0; i < 4; i++)
                    av[i] = *(const ulonglong2*)(hr + (i * 8) * H1S + k);
#pragma unroll
                for (int j = 0; j < 5; j++)
                    bv[j] = *(const ulonglong2*)(wc3 + j * W3S + k);
#pragma unroll
                for (int i = 0; i < 4; i++)
#pragma unroll
                    for (int j = 0; j < 5; j++) {
                        FMA2(acc[i][j], av[i].x, bv[j].x);
                        FMA2(acc[i][j], av[i].y, bv[j].y);
                    }
            }
            float p[4];
#pragma unroll
            for (int i = 0; i < 4; i++) {
                float s = 0.f;
#pragma unroll
                for (int j = 0; j < 5; j++) {
                    const float2 v = upk2(acc[i][j]);
                    s = fmaf(fsigmoid(v.x + v.y), w4sm[col0 + j], s);
                }
                // reduce over lcol (lane bits 3,4)
                s += __shfl_xor_sync(0xffffffffu, s, 8);
                s += __shfl_xor_sync(0xffffffffu, s, 16);
                p[i] = s;
            }
            if (lcol == 0) {
#pragma unroll
                for (int i = 0; i < 4; i++)
                    psm[wc * 64 + row0 + 8 * i] = p[i];
            }
        }
        __syncthreads();

        // ---- scores + mask ----
        if (tid < TSn) {
            const float sc = psm[tid] + psm[64 + tid] + s_b4;
            sbuf[tid] = (mask[b * Sn + sbase + t * TSn + tid] == 1) ? sc : PADV;
        }
        __syncthreads();

        // ---- tile max -> running max/scale ----
        if (tid < 32) {
            float m4 = fmaxf(sbuf[tid], sbuf[tid + 32]);
#pragma unroll
            for (int off = 16; off; off >>= 1)
                m4 = fmaxf(m4, __shfl_xor_sync(0xffffffffu, m4, off));
            if (tid == 0) {
                const float nm = fmaxf(s_m, m4);
                s_scale = __expf(s_m - nm);   // 0 on first tile
                s_m = nm;
            }
        }
        __syncthreads();

        // ---- weights + tile sum ----
        float wv = 0.f;
        if (tid < TSn) {
            wv = __expf(sbuf[tid] - s_m);
            wsm[tid] = wv;
        }
#pragma unroll
        for (int off = 16; off; off >>= 1)
            wv += __shfl_xor_sync(0xffffffffu, wv, off);
        if (tid < TSn && lane == 0) red[tid >> 5] = wv;
        __syncthreads();

        if (tid == 0) s_l = s_l * s_scale + red[0] + red[1];
        // ---- weighted accumulation (thread f = tid), 4 partial chains ----
        {
            float a0 = racc * s_scale, a1 = 0.f, a2 = 0.f, a3 = 0.f;
            const float* fc = fsm + tid;
#pragma unroll 4
            for (int s = 0; s < TSn; s += 4) {
                a0 = fmaf(wsm[s + 0], fc[(s + 0) * FSTRIDE], a0);
                a1 = fmaf(wsm[s + 1], fc[(s + 1) * FSTRIDE], a1);
                a2 = fmaf(wsm[s + 2], fc[(s + 2) * FSTRIDE], a2);
                a3 = fmaf(wsm[s + 3], fc[(s + 3) * FSTRIDE], a3);
            }
            racc = (a0 + a1) + (a2 + a3);
        }
        __syncthreads();   // protect fsm/wsm/psm before next tile
    }

    // ---- write flash partial (acc[128], m, l) ----
    float* part = g_part + cta * PARTW;
    part[tid] = racc;
    if (tid == 0) { part[128] = s_m; part[129] = s_l; }
}

// ---------------------------------------------------------------------------
__global__ __launch_bounds__(128) void combine_kernel(float* __restrict__ out)
{
    const int b = blockIdx.x, tid = threadIdx.x;
    const float* p0 = g_part + (2 * b) * PARTW;
    const float* p1 = g_part + (2 * b + 1) * PARTW;
    const float m0 = p0[128], l0 = p0[129];
    const float m1 = p1[128], l1 = p1[129];
    const float M = fmaxf(m0, m1);
    const float w0 = __expf(m0 - M), w1 = __expf(m1 - M);
    const float denom = w0 * l0 + w1 * l1;
    out[b * Fn + tid] = (w0 * p0[tid] + w1 * p1[tid]) / denom;
}

// ---------------------------------------------------------------------------
extern "C" void kernel_launch(void* const* d_in, const int* in_sizes, int n_in,
                              void* d_out, int out_size)
{
    const float* query = (const float*)d_in[0];
    const float* facts = (const float*)d_in[1];
    const int*   mask  = (const int*)  d_in[2];
    const float* W1    = (const float*)d_in[3];
    const float* b1    = (const float*)d_in[4];
    const float* alpha = (const float*)d_in[5];
    const float* W2    = (const float*)d_in[6];
    const float* b2    = (const float*)d_in[7];
    const float* W3    = (const float*)d_in[8];
    const float* b3    = (const float*)d_in[9];
    const float* W4    = (const float*)d_in[10];
    const float* b4    = (const float*)d_in[11];
    float* out = (float*)d_out;

    const int dyn_smem =
        (TSn * FSTRIDE + H1n * WS + TSn * H1S + H2n * W3S) * (int)sizeof(float); // 109056 B
    cudaFuncSetAttribute(din_kernel,
                         cudaFuncAttributeMaxDynamicSharedMemorySize, dyn_smem);

    din_kernel<<<Bn * 2, 128, dyn_smem>>>(query, facts, mask, W1, b1, alpha,
                                          W2, b2, W3, b3, W4, b4);
    combine_kernel<<<Bn, 128>>>(out);
}

// round 12
// speedup vs baseline: 1.7059x; 1.4518x over previous
#include <cuda_runtime.h>
#include <math_constants.h>
#include <stdint.h>

// attention_FCN: B=512, S=512, F=128, H1=80, H2=40
// din@W2 = qpre(b) + f @ Weff(b),  Weff = (W2b - W2c) + diag(q_b) @ W2d
// Round 11: R3 base (256 thr, 2 CTA/SM, f32x2 GEMM1 4x5) +
//   GEMM2 on 128 threads with 4x5 tiles (1.8 B/MAC vs 4.4),
//   epilogue from global (L2), cp.async prefetch of next facts tile.

#define Bn   512
#define Sn   512
#define Fn   128
#define H1n  80
#define H2n  40
#define TSn  64
#define NTn  (Sn / TSn)
#define FSTRIDE 132     // facts smem row stride (16B-aligned, conflict-free)
#define WS      132     // weffT row stride (k-major)
#define H1S     84      // h1 row stride
#define W3S     80      // w3T row stride (k-major)
#define PADV (-4294967295.0f)

__device__ __forceinline__ unsigned long long pk2(float lo, float hi) {
    unsigned long long r;
    asm("mov.b64 %0, {%1,%2};" : "=l"(r) : "f"(lo), "f"(hi));
    return r;
}
__device__ __forceinline__ float2 upk2(unsigned long long v) {
    float2 r;
    asm("mov.b64 {%0,%1}, %2;" : "=f"(r.x), "=f"(r.y) : "l"(v));
    return r;
}
#define FMA2(d, a, b) \
    asm("fma.rn.f32x2 %0, %1, %2, %0;" : "+l"(d) : "l"(a), "l"(b))

__device__ __forceinline__ float fsigmoid(float x) {
    return __fdividef(1.f, 1.f + __expf(-x));
}
__device__ __forceinline__ uint32_t smem_u32(const void* p) {
    uint32_t a;
    asm("{ .reg .u64 t; cvta.to.shared.u64 t, %1; cvt.u32.u64 %0, t; }"
        : "=r"(a) : "l"(p));
    return a;
}
// async copy 16B global -> shared (LDGSTS)
__device__ __forceinline__ void cpa16(uint32_t dst, const float* src) {
    asm volatile("cp.async.cg.shared.global [%0], [%1], 16;"
                 :: "r"(dst), "l"(src) : "memory");
}
#define CPA_COMMIT() asm volatile("cp.async.commit_group;" ::: "memory")
#define CPA_WAIT0()  asm volatile("cp.async.wait_group 0;" ::: "memory")

// ---------------------------------------------------------------------------
__global__ __launch_bounds__(256, 2) void din_kernel(
    const float* __restrict__ query,
    const float* __restrict__ facts,
    const int*   __restrict__ mask,
    const float* __restrict__ W1,
    const float* __restrict__ b1,
    const float* __restrict__ alpha,
    const float* __restrict__ W2,
    const float* __restrict__ b2,
    const float* __restrict__ W3,
    const float* __restrict__ b3,
    const float* __restrict__ W4,
    const float* __restrict__ b4,
    float* __restrict__ out)
{
    extern __shared__ float dyn[];
    float* fsm   = dyn;                     // 64*132
    float* weffT = fsm + TSn * FSTRIDE;     // 80*132 (k-major)
    float* h1sm  = weffT + H1n * WS;        // 64*84
    float* w3T   = h1sm + TSn * H1S;        // 40*80  (k-major)

    __shared__ float qsm[Fn];
    __shared__ float qprem[H1n];
    __shared__ float w4sm[H2n];
    __shared__ float b3sm[H2n];
    __shared__ float psm[4 * TSn];          // GEMM2 partials / final combine
    __shared__ float sbuf[TSn];             // masked scores
    __shared__ float wsm[TSn];              // softmax weights
    __shared__ float red[2];
    __shared__ float s_m, s_l, s_scale, s_b4;

    const int b    = blockIdx.x;
    const int tid  = threadIdx.x;
    const int lane = tid & 31;
    const uint32_t fsm_base = smem_u32(fsm);
    const float* factsb = facts + (size_t)b * Sn * Fn;

    // ---- kick off async load of facts tile 0 (overlaps whole prologue) ----
    {
#pragma unroll
        for (int it = 0; it < 8; it++) {
            const int idx = it * 256 + tid;          // 2048 float4 total
            const int row = idx >> 5, c4 = idx & 31;
            cpa16(fsm_base + (uint32_t)(row * FSTRIDE + c4 * 4) * 4u,
                  factsb + idx * 4);
        }
        CPA_COMMIT();
    }

    // ---- prologue ----
    if (tid < Fn) qsm[tid] = query[b * Fn + tid];    // qsm = qin (temporarily)
    if (tid == 0) { s_m = -CUDART_INF_F; s_l = 0.f; s_b4 = b4[0]; }
    if (tid < H2n) { w4sm[tid] = W4[tid]; b3sm[tid] = b3[tid]; }
    for (int i = tid; i < H1n * H2n; i += 256) {     // w3T[h2][k] = W3[k][h2]
        const int h2 = i % H2n, k = i / H2n;
        w3T[h2 * W3S + k] = W3[i];
    }
    __syncthreads();

    // q = PReLU(query @ W1 + b1)
    float qv = 0.f;
    if (tid < Fn) {
        float a0 = b1[tid], a1 = 0.f, a2 = 0.f, a3 = 0.f;
#pragma unroll 4
        for (int k = 0; k < Fn; k += 4) {
            a0 = fmaf(qsm[k + 0], W1[(k + 0) * Fn + tid], a0);
            a1 = fmaf(qsm[k + 1], W1[(k + 1) * Fn + tid], a1);
            a2 = fmaf(qsm[k + 2], W1[(k + 2) * Fn + tid], a2);
            a3 = fmaf(qsm[k + 3], W1[(k + 3) * Fn + tid], a3);
        }
        const float acc = (a0 + a1) + (a2 + a3);
        qv = (acc >= 0.f) ? acc : alpha[tid] * acc;
    }
    __syncthreads();
    if (tid < Fn) qsm[tid] = qv;
    __syncthreads();

    // qpre[h] = b2[h] + sum_k q[k]*(W2a+W2c)[k,h]
    if (tid < H1n) {
        float a0 = b2[tid], a1 = 0.f;
#pragma unroll 4
        for (int k = 0; k < Fn; k += 2) {
            a0 = fmaf(qsm[k+0], W2[(k+0)*H1n + tid] + W2[(2*Fn + k+0)*H1n + tid], a0);
            a1 = fmaf(qsm[k+1], W2[(k+1)*H1n + tid] + W2[(2*Fn + k+1)*H1n + tid], a1);
        }
        qprem[tid] = a0 + a1;
    }
    // weffT[h][k] = (W2b - W2c)[k,h] + q[k]*W2d[k,h]  (k-major rows)
    for (int i = tid; i < Fn * H1n; i += 256) {
        const int k = i / H1n, h = i - k * H1n;
        const float wbc = W2[(Fn + k) * H1n + h] - W2[(2 * Fn + k) * H1n + h];
        const float wd  = W2[(3 * Fn + k) * H1n + h];
        weffT[h * WS + k] = fmaf(qsm[k], wd, wbc);
    }
    CPA_WAIT0();          // facts tile 0 landed
    __syncthreads();

    const int tx = tid & 15;   // GEMM1: 16 col-groups of 5
    const int ty = tid >> 4;   // GEMM1: 16 row-groups of 4
    const int ef = tid & 127;  // epilogue feature
    const int eh = tid >> 7;   // epilogue s-half (0: s<32, 1: s>=32)

    float racc = 0.f;

    for (int t = 0; t < NTn; t++) {
        // ---- GEMM1: h1 = sigmoid(qpre + f @ Weff), 4x5/thread, f32x2 ----
        {
            unsigned long long acc2[4][5];
#pragma unroll
            for (int i = 0; i < 4; i++)
#pragma unroll
                for (int j = 0; j < 5; j++)
                    acc2[i][j] = pk2(qprem[tx * 5 + j], 0.f);

            const float* fr = fsm   + (ty * 4) * FSTRIDE;
            const float* wb = weffT + (tx * 5) * WS;
#pragma unroll 2
            for (int k = 0; k < Fn; k += 4) {
                ulonglong2 av[4], bv[5];
#pragma unroll
                for (int i = 0; i < 4; i++)
                    av[i] = *(const ulonglong2*)(fr + i * FSTRIDE + k);
#pragma unroll
                for (int j = 0; j < 5; j++)
                    bv[j] = *(const ulonglong2*)(wb + j * WS + k);
#pragma unroll
                for (int i = 0; i < 4; i++)
#pragma unroll
                    for (int j = 0; j < 5; j++) {
                        FMA2(acc2[i][j], av[i].x, bv[j].x);
                        FMA2(acc2[i][j], av[i].y, bv[j].y);
                    }
            }
#pragma unroll
            for (int i = 0; i < 4; i++)
#pragma unroll
                for (int j = 0; j < 5; j++) {
                    const float2 v = upk2(acc2[i][j]);
                    h1sm[(ty * 4 + i) * H1S + tx * 5 + j] = fsigmoid(v.x + v.y);
                }
        }
        __syncthreads();    // h1 ready; all fsm(t) reads done

        // ---- prefetch facts tile t+1 into fsm (async, overlapped) ----
        if (t + 1 < NTn) {
            const float* nsrc = factsb + (size_t)(t + 1) * TSn * Fn;
#pragma unroll
            for (int it = 0; it < 8; it++) {
                const int idx = it * 256 + tid;
                const int row = idx >> 5, c4 = idx & 31;
                cpa16(fsm_base + (uint32_t)(row * FSTRIDE + c4 * 4) * 4u,
                      nsrc + idx * 4);
            }
            CPA_COMMIT();
        }

        // ---- GEMM2: 128 threads, 4 rows x 5 cols per thread ----
        if (tid < 128) {
            const int rowg = tid & 15;      // rows rowg*4 .. +3
            const int colg = tid >> 4;      // cols colg*5 .. +4
            unsigned long long acc2[4][5];
#pragma unroll
            for (int j = 0; j < 5; j++) {
                const unsigned long long z = pk2(b3sm[colg * 5 + j], 0.f);
#pragma unroll
                for (int i = 0; i < 4; i++) acc2[i][j] = z;
            }
            const float* hr = h1sm + (rowg * 4) * H1S;
            const float* wc = w3T + (colg * 5) * W3S;
#pragma unroll 2
            for (int k = 0; k < H1n; k += 4) {
                ulonglong2 av[4], bv[5];
#pragma unroll
                for (int i = 0; i < 4; i++)
                    av[i] = *(const ulonglong2*)(hr + i * H1S + k);
#pragma unroll
                for (int j = 0; j < 5; j++)
                    bv[j] = *(const ulonglong2*)(wc + j * W3S + k);
#pragma unroll
                for (int i = 0; i < 4; i++)
#pragma unroll
                    for (int j = 0; j < 5; j++) {
                        FMA2(acc2[i][j], av[i].x, bv[j].x);
                        FMA2(acc2[i][j], av[i].y, bv[j].y);
                    }
            }
            // sigmoid + dot W4 -> p[i]; reduce colg pairs via shfl
#pragma unroll
            for (int i = 0; i < 4; i++) {
                float p = 0.f;
#pragma unroll
                for (int j = 0; j < 5; j++) {
                    const float2 v = upk2(acc2[i][j]);
                    p = fmaf(fsigmoid(v.x + v.y), w4sm[colg * 5 + j], p);
                }
                p += __shfl_xor_sync(0xffffffffu, p, 16);   // colg pair
                if ((tid & 16) == 0)
                    psm[(tid >> 5) * TSn + rowg * 4 + i] = p;
            }
        }
        __syncthreads();

        // ---- scores + mask (tid<64) ----
        if (tid < TSn) {
            const float sc = psm[tid] + psm[TSn + tid] + psm[2 * TSn + tid]
                           + psm[3 * TSn + tid] + s_b4;
            sbuf[tid] = (mask[b * Sn + t * TSn + tid] == 1) ? sc : PADV;
        }
        __syncthreads();

        // ---- tile max -> running max/scale ----
        if (tid < 32) {
            float m4 = fmaxf(sbuf[tid], sbuf[tid + 32]);
#pragma unroll
            for (int off = 16; off; off >>= 1)
                m4 = fmaxf(m4, __shfl_xor_sync(0xffffffffu, m4, off));
            if (tid == 0) {
                const float nm = fmaxf(s_m, m4);
                s_scale = __expf(s_m - nm);     // 0 on first tile
                s_m = nm;
            }
        }
        __syncthreads();

        // ---- weights + tile sum ----
        float wv = 0.f;
        if (tid < TSn) {
            wv = __expf(sbuf[tid] - s_m);
            wsm[tid] = wv;
        }
#pragma unroll
        for (int off = 16; off; off >>= 1)
            wv += __shfl_xor_sync(0xffffffffu, wv, off);
        if (tid < TSn && lane == 0) red[tid >> 5] = wv;
        __syncthreads();

        if (tid == 0) s_l = s_l * s_scale + red[0] + red[1];

        // ---- epilogue: weighted facts from GLOBAL (L2-hot), 4 chains ----
        {
            const float* fb = factsb + (size_t)(t * TSn + eh * 32) * Fn + ef;
            const float* wp = wsm + eh * 32;
            float a0 = racc * s_scale, a1 = 0.f, a2 = 0.f, a3 = 0.f;
#pragma unroll 4
            for (int s = 0; s < 32; s += 4) {
                a0 = fmaf(wp[s + 0], fb[(size_t)(s + 0) * Fn], a0);
                a1 = fmaf(wp[s + 1], fb[(size_t)(s + 1) * Fn], a1);
                a2 = fmaf(wp[s + 2], fb[(size_t)(s + 2) * Fn], a2);
                a3 = fmaf(wp[s + 3], fb[(size_t)(s + 3) * Fn], a3);
            }
            racc = (a0 + a1) + (a2 + a3);
        }

        CPA_WAIT0();        // fsm(t+1) complete
        __syncthreads();    // wsm/psm reads done; fsm stable for next GEMM1
    }

    // ---- combine the two s-halves, write output ----
    if (eh == 1) psm[ef] = racc;
    __syncthreads();
    if (eh == 0)
        out[b * Fn + ef] = (racc + psm[ef]) / s_l;
}

// ---------------------------------------------------------------------------
extern "C" void kernel_launch(void* const* d_in, const int* in_sizes, int n_in,
                              void* d_out, int out_size)
{
    const float* query = (const float*)d_in[0];
    const float* facts = (const float*)d_in[1];
    const int*   mask  = (const int*)  d_in[2];
    const float* W1    = (const float*)d_in[3];
    const float* b1    = (const float*)d_in[4];
    const float* alpha = (const float*)d_in[5];
    const float* W2    = (const float*)d_in[6];
    const float* b2    = (const float*)d_in[7];
    const float* W3    = (const float*)d_in[8];
    const float* b3    = (const float*)d_in[9];
    const float* W4    = (const float*)d_in[10];
    const float* b4    = (const float*)d_in[11];
    float* out = (float*)d_out;

    const int dyn_smem =
        (TSn * FSTRIDE + H1n * WS + TSn * H1S + H2n * W3S) * (int)sizeof(float); // 110336 B
    cudaFuncSetAttribute(din_kernel,
                         cudaFuncAttributeMaxDynamicSharedMemorySize, dyn_smem);

    din_kernel<<<Bn, 256, dyn_smem>>>(query, facts, mask, W1, b1, alpha,
                                      W2, b2, W3, b3, W4, b4, out);
}